// round 2
// baseline (speedup 1.0000x reference)
#include <cuda_runtime.h>
#include <math.h>

// ---------------- problem constants ----------------
#define NQ   10000
#define DIM  256
#define NH   8
#define HD   32
#define PT   4
#define PP   4
#define PSS  4
#define NC   6
#define HF   24
#define WF   60
#define BHH  100
#define BWW  100
#define DFF  1024
#define T_RAD 0.15f
#define S_RAD 0.12f

// ---------------- scratch (device globals; no allocation allowed) ----------
__device__ __align__(256) float g_ai[NQ * 512];        // [pb(256) | q1(256)] per row
__device__ __align__(256) float g_toff[NQ * 128];      // raw temporal offsets
__device__ __align__(256) float g_twl[NQ * 64];        // temporal weight logits
__device__ __align__(256) float g_tfused[NQ * DIM];
__device__ __align__(256) float g_x[NQ * DIM];
__device__ __align__(256) float g_q2[NQ * DIM];
__device__ __align__(256) float g_soff[NQ * 256];      // raw spatial offsets
__device__ __align__(256) float g_swl[NQ * 128];       // spatial weight logits
__device__ __align__(256) float g_sfused[NQ * DIM];
__device__ __align__(256) float g_x2[NQ * DIM];
__device__ __align__(256) float g_q3[NQ * DIM];
__device__ __align__(256) float g_h[NQ * DFF];
__device__ __align__(256) float g_feats[NC * HF * WF * DIM]; // [NC][H*W][256]
__device__ int g_mask_mode; // 0=u8, 1=i32, 2=f32

// ---------------- reductions ----------------
__device__ __forceinline__ float blockSum256(float v, float* sm) {
    #pragma unroll
    for (int o = 16; o > 0; o >>= 1) v += __shfl_down_sync(0xffffffffu, v, o);
    int w = threadIdx.x >> 5;
    if ((threadIdx.x & 31) == 0) sm[w] = v;
    __syncthreads();
    if (threadIdx.x < 32) {
        float x = (threadIdx.x < 8) ? sm[threadIdx.x] : 0.f;
        #pragma unroll
        for (int o = 4; o > 0; o >>= 1) x += __shfl_down_sync(0xffffffffu, x, o);
        if (threadIdx.x == 0) sm[0] = x;
    }
    __syncthreads();
    float r = sm[0];
    __syncthreads();
    return r;
}

// ---------------- layernorm kernels ----------------
__global__ void ln1_kernel(const float* __restrict__ q, const float* __restrict__ p,
                           const float* __restrict__ g, const float* __restrict__ b) {
    int n = blockIdx.x, t = threadIdx.x;
    __shared__ float sm[8];
    float gv = g[t], bv = b[t];
    float vq = q[(size_t)n * DIM + t];
    float vp = p[(size_t)n * DIM + t];
    float muq = blockSum256(vq, sm) * (1.f / DIM);
    float dq = vq - muq;
    float varq = blockSum256(dq * dq, sm) * (1.f / DIM);
    float mup = blockSum256(vp, sm) * (1.f / DIM);
    float dp = vp - mup;
    float varp = blockSum256(dp * dp, sm) * (1.f / DIM);
    g_ai[(size_t)n * 512 + t]       = dp * rsqrtf(varp + 1e-5f) * gv + bv; // pb
    g_ai[(size_t)n * 512 + 256 + t] = dq * rsqrtf(varq + 1e-5f) * gv + bv; // q1
}

__global__ void ln_kernel(const float* __restrict__ in, const float* __restrict__ g,
                          const float* __restrict__ b, float* __restrict__ out) {
    int n = blockIdx.x, t = threadIdx.x;
    __shared__ float sm[8];
    float v = in[(size_t)n * DIM + t];
    float mu = blockSum256(v, sm) * (1.f / DIM);
    float d = v - mu;
    float var = blockSum256(d * d, sm) * (1.f / DIM);
    out[(size_t)n * DIM + t] = d * rsqrtf(var + 1e-5f) * g[t] + b[t];
}

// ---------------- feature transpose [NC][256][1440] -> [NC][1440][256] ----
__global__ void transpose_feats(const float* __restrict__ in) {
    __shared__ float tile[32][33];
    int c = blockIdx.z;
    int p0 = blockIdx.x * 32, ch0 = blockIdx.y * 32;
    int tx = threadIdx.x, ty = threadIdx.y; // 32x8
    #pragma unroll
    for (int r = ty; r < 32; r += 8)
        tile[r][tx] = in[((size_t)c * DIM + ch0 + r) * (HF * WF) + p0 + tx];
    __syncthreads();
    #pragma unroll
    for (int r = ty; r < 32; r += 8)
        g_feats[((size_t)c * (HF * WF) + p0 + r) * DIM + ch0 + tx] = tile[tx][r];
}

// ---------------- mask dtype detection ----------------
__global__ void detect_mask(const unsigned char* __restrict__ m, int nbytes) {
    __shared__ int ge2, odd1;
    if (threadIdx.x == 0) { ge2 = 0; odd1 = 0; }
    __syncthreads();
    for (int i = threadIdx.x; i < nbytes; i += blockDim.x) {
        unsigned char v = m[i];
        if (v >= 2) atomicOr(&ge2, 1);
        if (v == 1 && (i & 3)) atomicOr(&odd1, 1);
    }
    __syncthreads();
    if (threadIdx.x == 0) g_mask_mode = ge2 ? 2 : (odd1 ? 0 : 1);
}

// ---------------- bilinear gather (channel-per-lane) ----------------
__device__ __forceinline__ float bilin(const float* __restrict__ src, int rstride,
                                       int H, int W, float lx, float ly) {
    float ix = lx * W - 0.5f, iy = ly * H - 0.5f;
    float x0f = floorf(ix), y0f = floorf(iy);
    float wx = ix - x0f, wy = iy - y0f;
    int x0 = (int)x0f, y0 = (int)y0f, x1 = x0 + 1, y1 = y0 + 1;
    bool vx0 = (x0 >= 0) & (x0 < W), vx1 = (x1 >= 0) & (x1 < W);
    bool vy0 = (y0 >= 0) & (y0 < H), vy1 = (y1 >= 0) & (y1 < H);
    float v = 0.f;
    if (vy0) {
        if (vx0) v += (1.f - wx) * (1.f - wy) * __ldg(src + ((size_t)y0 * W + x0) * rstride);
        if (vx1) v += wx * (1.f - wy) * __ldg(src + ((size_t)y0 * W + x1) * rstride);
    }
    if (vy1) {
        if (vx0) v += (1.f - wx) * wy * __ldg(src + ((size_t)y1 * W + x0) * rstride);
        if (vx1) v += wx * wy * __ldg(src + ((size_t)y1 * W + x1) * rstride);
    }
    return v;
}

// ---------------- temporal deformable sampling ----------------
__global__ void temporal_kernel(const float* __restrict__ ref2d, const float* __restrict__ ego) {
    int n = blockIdx.x;
    int head = threadIdx.x >> 5, lane = threadIdx.x & 31;
    float rx = __ldg(ref2d + (size_t)n * 2 + 0);
    float ry = __ldg(ref2d + (size_t)n * 2 + 1);
    float acc = 0.f;
    #pragma unroll
    for (int si = 0; si < 2; si++) {
        float l[PT], mx = -1e30f, se = 0.f;
        #pragma unroll
        for (int pt = 0; pt < PT; pt++) {
            l[pt] = g_twl[(size_t)n * 64 + si * 32 + head * 4 + pt];
            mx = fmaxf(mx, l[pt]);
        }
        #pragma unroll
        for (int pt = 0; pt < PT; pt++) { l[pt] = __expf(l[pt] - mx); se += l[pt]; }
        float inv = 1.f / se;
        float bx = rx + (si == 0 ? __ldg(ego + 0) : 0.f);
        float by = ry + (si == 0 ? __ldg(ego + 1) : 0.f);
        const float* src = g_ai + (si == 0 ? 0 : 256) + head * 32 + lane; // row stride 512
        #pragma unroll
        for (int pt = 0; pt < PT; pt++) {
            float ox = tanhf(g_toff[(size_t)n * 128 + si * 64 + head * 8 + pt * 2 + 0]) * T_RAD;
            float oy = tanhf(g_toff[(size_t)n * 128 + si * 64 + head * 8 + pt * 2 + 1]) * T_RAD;
            acc += l[pt] * inv * bilin(src, 512, BHH, BWW, bx + ox, by + oy);
        }
    }
    g_tfused[(size_t)n * DIM + head * 32 + lane] = acc * 0.5f;
}

// ---------------- spatial deformable cross-attention ----------------
__global__ void spatial_kernel(const float* __restrict__ refcam,
                               const unsigned char* __restrict__ mask) {
    int n = blockIdx.x;
    int head = threadIdx.x >> 5, lane = threadIdx.x & 31;
    int mode = g_mask_mode;
    float acc = 0.f;
    int cnt = 0;
    for (int c = 0; c < NC; c++) {
        bool vis[PP];
        bool any = false;
        #pragma unroll
        for (int pp = 0; pp < PP; pp++) {
            size_t mi = ((size_t)c * NQ + n) * PP + pp;
            bool v;
            if (mode == 0)      v = mask[mi] != 0;
            else if (mode == 1) v = ((const int*)mask)[mi] != 0;
            else                v = ((const float*)mask)[mi] != 0.f;
            vis[pp] = v;
            any |= v;
        }
        if (!any) continue;
        cnt++;
        float e[16];
        float mx = -1e30f, se = 0.f;
        #pragma unroll
        for (int p = 0; p < 16; p++) {
            if (vis[p >> 2]) {
                e[p] = g_swl[(size_t)n * 128 + head * 16 + p];
                mx = fmaxf(mx, e[p]);
            } else e[p] = -1e30f;
        }
        #pragma unroll
        for (int p = 0; p < 16; p++) {
            e[p] = vis[p >> 2] ? __expf(e[p] - mx) : 0.f;
            se += e[p];
        }
        float inv = 1.f / se;
        const float* src = g_feats + (size_t)c * (HF * WF * DIM) + head * 32 + lane;
        #pragma unroll
        for (int p = 0; p < 16; p++) {
            if (!vis[p >> 2]) continue;
            int pp = p >> 2;
            float lx = __ldg(refcam + (((size_t)c * NQ + n) * PP + pp) * 2 + 0)
                     + tanhf(g_soff[(size_t)n * 256 + head * 32 + p * 2 + 0]) * S_RAD;
            float ly = __ldg(refcam + (((size_t)c * NQ + n) * PP + pp) * 2 + 1)
                     + tanhf(g_soff[(size_t)n * 256 + head * 32 + p * 2 + 1]) * S_RAD;
            acc += e[p] * inv * bilin(src, DIM, HF, WF, lx, ly);
        }
    }
    g_sfused[(size_t)n * DIM + head * 32 + lane] = acc / (float)(cnt > 0 ? cnt : 1);
}

// ---------------- SGEMM: C[M,N] = A[M,K] @ B[K,N] + bias (+res) (relu?) ----
#define BM 128
#define BN 128
#define BK 8
__global__ void sgemm_kernel(const float* __restrict__ A, const float* __restrict__ B,
                             const float* __restrict__ bias, const float* __restrict__ res,
                             float* __restrict__ C, int M, int N, int K, int relu) {
    __shared__ __align__(16) float As[BK][BM];
    __shared__ __align__(16) float Bs[BK][BN];
    int tid = threadIdx.x;
    int bm = blockIdx.y * BM;
    int bn = blockIdx.x * BN;

    int arow = tid >> 1;              // 0..127
    int acol = (tid & 1) << 2;        // 0 or 4
    int brow = tid >> 5;              // 0..7
    int bcol = (tid & 31) << 2;       // 0..124

    int tx = tid & 15, ty = tid >> 4; // 16x16

    float acc[8][8];
    #pragma unroll
    for (int i = 0; i < 8; i++)
        #pragma unroll
        for (int j = 0; j < 8; j++) acc[i][j] = 0.f;

    for (int k0 = 0; k0 < K; k0 += BK) {
        float4 av = make_float4(0.f, 0.f, 0.f, 0.f);
        if (bm + arow < M)
            av = *(const float4*)(A + (size_t)(bm + arow) * K + k0 + acol);
        As[acol + 0][arow] = av.x;
        As[acol + 1][arow] = av.y;
        As[acol + 2][arow] = av.z;
        As[acol + 3][arow] = av.w;

        float4 bv = make_float4(0.f, 0.f, 0.f, 0.f);
        if (bn + bcol < N)
            bv = *(const float4*)(B + (size_t)(k0 + brow) * N + bn + bcol);
        *(float4*)&Bs[brow][bcol] = bv;
        __syncthreads();

        #pragma unroll
        for (int kk = 0; kk < BK; kk++) {
            float a[8], b[8];
            *(float4*)&a[0] = *(const float4*)&As[kk][ty * 4];
            *(float4*)&a[4] = *(const float4*)&As[kk][64 + ty * 4];
            *(float4*)&b[0] = *(const float4*)&Bs[kk][tx * 4];
            *(float4*)&b[4] = *(const float4*)&Bs[kk][64 + tx * 4];
            #pragma unroll
            for (int i = 0; i < 8; i++)
                #pragma unroll
                for (int j = 0; j < 8; j++)
                    acc[i][j] += a[i] * b[j];
        }
        __syncthreads();
    }

    #pragma unroll
    for (int i = 0; i < 8; i++) {
        int row = bm + ((i < 4) ? (ty * 4 + i) : (64 + ty * 4 + i - 4));
        if (row >= M) continue;
        #pragma unroll
        for (int j = 0; j < 8; j++) {
            int col = bn + ((j < 4) ? (tx * 4 + j) : (64 + tx * 4 + j - 4));
            if (col >= N) continue;
            float v = acc[i][j] + __ldg(bias + col);
            if (res) v += res[(size_t)row * N + col];
            if (relu) v = fmaxf(v, 0.f);
            C[(size_t)row * N + col] = v;
        }
    }
}

static inline void sgemm(const float* A, const float* B, const float* bias, const float* res,
                         float* C, int M, int N, int K, int relu) {
    dim3 grid((N + BN - 1) / BN, (M + BM - 1) / BM);
    sgemm_kernel<<<grid, 256>>>(A, B, bias, res, C, M, N, K, relu);
}

// ---------------- launch ----------------
extern "C" void kernel_launch(void* const* d_in, const int* in_sizes, int n_in,
                              void* d_out, int out_size) {
    const float* query   = (const float*)d_in[0];
    const float* prevbev = (const float*)d_in[1];
    const float* imfeats = (const float*)d_in[2];
    const float* ref2d   = (const float*)d_in[3];
    const float* refcam  = (const float*)d_in[4];
    const float* ego     = (const float*)d_in[5];
    const float* t_off_w = (const float*)d_in[6];
    const float* t_off_b = (const float*)d_in[7];
    const float* t_wt_w  = (const float*)d_in[8];
    const float* t_wt_b  = (const float*)d_in[9];
    const float* t_out_w = (const float*)d_in[10];
    const float* t_out_b = (const float*)d_in[11];
    const float* s_off_w = (const float*)d_in[12];
    const float* s_off_b = (const float*)d_in[13];
    const float* s_wt_w  = (const float*)d_in[14];
    const float* s_wt_b  = (const float*)d_in[15];
    const float* s_out_w = (const float*)d_in[16];
    const float* s_out_b = (const float*)d_in[17];
    const float* ffn_w1  = (const float*)d_in[18];
    const float* ffn_b1  = (const float*)d_in[19];
    const float* ffn_w2  = (const float*)d_in[20];
    const float* ffn_b2  = (const float*)d_in[21];
    const float* ln1_g   = (const float*)d_in[22];
    const float* ln1_b   = (const float*)d_in[23];
    const float* ln2_g   = (const float*)d_in[24];
    const float* ln2_b   = (const float*)d_in[25];
    const float* ln3_g   = (const float*)d_in[26];
    const float* ln3_b   = (const float*)d_in[27];
    const unsigned char* bev_mask = (const unsigned char*)d_in[28];

    float *ai, *toff, *twl, *tfused, *x, *q2, *soff, *swl, *sfused, *x2, *q3, *h;
    cudaGetSymbolAddress((void**)&ai, g_ai);
    cudaGetSymbolAddress((void**)&toff, g_toff);
    cudaGetSymbolAddress((void**)&twl, g_twl);
    cudaGetSymbolAddress((void**)&tfused, g_tfused);
    cudaGetSymbolAddress((void**)&x, g_x);
    cudaGetSymbolAddress((void**)&q2, g_q2);
    cudaGetSymbolAddress((void**)&soff, g_soff);
    cudaGetSymbolAddress((void**)&swl, g_swl);
    cudaGetSymbolAddress((void**)&sfused, g_sfused);
    cudaGetSymbolAddress((void**)&x2, g_x2);
    cudaGetSymbolAddress((void**)&q3, g_q3);
    cudaGetSymbolAddress((void**)&h, g_h);

    // 1) LN(query), LN(prev_bev) -> ai = [pb | q1]   (also the BEV maps, [H,W,C])
    ln1_kernel<<<NQ, 256>>>(query, prevbev, ln1_g, ln1_b);

    // prep: image feature transpose + mask dtype detection (independent)
    transpose_feats<<<dim3(45, 8, NC), dim3(32, 8)>>>(imfeats);
    detect_mask<<<1, 256>>>(bev_mask, NC * NQ * PP);

    // 2) temporal offset / weight projections
    sgemm(ai, t_off_w, t_off_b, nullptr, toff, NQ, 128, 512, 0);
    sgemm(ai, t_wt_w, t_wt_b, nullptr, twl, NQ, 64, 512, 0);

    // 3) temporal deformable sampling
    temporal_kernel<<<NQ, 256>>>(ref2d, ego);

    // 4) x = query + tfused @ t_out_w + b
    sgemm(tfused, t_out_w, t_out_b, query, x, NQ, DIM, DIM, 0);

    // 5) q2 = LN2(x)
    ln_kernel<<<NQ, 256>>>(x, ln2_g, ln2_b, q2);

    // 6) spatial offset / weight projections
    sgemm(q2, s_off_w, s_off_b, nullptr, soff, NQ, 256, DIM, 0);
    sgemm(q2, s_wt_w, s_wt_b, nullptr, swl, NQ, 128, DIM, 0);

    // 7) spatial deformable cross-attention over 6 cameras
    spatial_kernel<<<NQ, 256>>>(refcam, bev_mask);

    // 8) x2 = x + sfused @ s_out_w + b
    sgemm(sfused, s_out_w, s_out_b, x, x2, NQ, DIM, DIM, 0);

    // 9) q3 = LN3(x2); h = relu(q3 @ ffn_w1 + b1); out = x2 + h @ ffn_w2 + b2
    ln_kernel<<<NQ, 256>>>(x2, ln3_g, ln3_b, q3);
    sgemm(q3, ffn_w1, ffn_b1, nullptr, h, NQ, DFF, DIM, 1);
    sgemm(h, ffn_w2, ffn_b2, x2, (float*)d_out, NQ, DIM, DFF, 0);
}

// round 3
// speedup vs baseline: 1.0341x; 1.0341x over previous
#include <cuda_runtime.h>
#include <math.h>

// ---------------- problem constants ----------------
#define NQ   10000
#define DIM  256
#define NH   8
#define HD   32
#define PT   4
#define PP   4
#define PSS  4
#define NC   6
#define HF   24
#define WF   60
#define BHH  100
#define BWW  100
#define DFF  1024
#define T_RAD 0.15f
#define S_RAD 0.12f

// ---------------- scratch (device globals; no allocation allowed) ----------
__device__ __align__(256) float g_ai[NQ * 512];        // [pb(256) | q1(256)] per row
__device__ __align__(256) float g_toff[NQ * 128];      // raw temporal offsets
__device__ __align__(256) float g_twl[NQ * 64];        // temporal weight logits
__device__ __align__(256) float g_tfused[NQ * DIM];
__device__ __align__(256) float g_x[NQ * DIM];
__device__ __align__(256) float g_q2[NQ * DIM];
__device__ __align__(256) float g_soff[NQ * 256];      // raw spatial offsets
__device__ __align__(256) float g_swl[NQ * 128];       // spatial weight logits
__device__ __align__(256) float g_sfused[NQ * DIM];
__device__ __align__(256) float g_x2[NQ * DIM];
__device__ __align__(256) float g_q3[NQ * DIM];
__device__ __align__(256) float g_h[NQ * DFF];
__device__ __align__(256) float g_feats[NC * HF * WF * DIM]; // [NC][H*W][256]
__device__ int g_mask_mode; // 0=u8, 1=i32, 2=f32

// ---------------- reductions ----------------
__device__ __forceinline__ float blockSum256(float v, float* sm) {
    #pragma unroll
    for (int o = 16; o > 0; o >>= 1) v += __shfl_down_sync(0xffffffffu, v, o);
    int w = threadIdx.x >> 5;
    if ((threadIdx.x & 31) == 0) sm[w] = v;
    __syncthreads();
    if (threadIdx.x < 32) {
        float x = (threadIdx.x < 8) ? sm[threadIdx.x] : 0.f;
        #pragma unroll
        for (int o = 4; o > 0; o >>= 1) x += __shfl_down_sync(0xffffffffu, x, o);
        if (threadIdx.x == 0) sm[0] = x;
    }
    __syncthreads();
    float r = sm[0];
    __syncthreads();
    return r;
}

// ---------------- layernorm kernels ----------------
__global__ void ln1_kernel(const float* __restrict__ q, const float* __restrict__ p,
                           const float* __restrict__ g, const float* __restrict__ b) {
    int n = blockIdx.x, t = threadIdx.x;
    __shared__ float sm[8];
    float gv = g[t], bv = b[t];
    float vq = q[(size_t)n * DIM + t];
    float vp = p[(size_t)n * DIM + t];
    float muq = blockSum256(vq, sm) * (1.f / DIM);
    float dq = vq - muq;
    float varq = blockSum256(dq * dq, sm) * (1.f / DIM);
    float mup = blockSum256(vp, sm) * (1.f / DIM);
    float dp = vp - mup;
    float varp = blockSum256(dp * dp, sm) * (1.f / DIM);
    g_ai[(size_t)n * 512 + t]       = dp * rsqrtf(varp + 1e-5f) * gv + bv; // pb
    g_ai[(size_t)n * 512 + 256 + t] = dq * rsqrtf(varq + 1e-5f) * gv + bv; // q1
}

__global__ void ln_kernel(const float* __restrict__ in, const float* __restrict__ g,
                          const float* __restrict__ b, float* __restrict__ out) {
    int n = blockIdx.x, t = threadIdx.x;
    __shared__ float sm[8];
    float v = in[(size_t)n * DIM + t];
    float mu = blockSum256(v, sm) * (1.f / DIM);
    float d = v - mu;
    float var = blockSum256(d * d, sm) * (1.f / DIM);
    out[(size_t)n * DIM + t] = d * rsqrtf(var + 1e-5f) * g[t] + b[t];
}

// ---------------- feature transpose [NC][256][1440] -> [NC][1440][256] ----
__global__ void transpose_feats(const float* __restrict__ in) {
    __shared__ float tile[32][33];
    int c = blockIdx.z;
    int p0 = blockIdx.x * 32, ch0 = blockIdx.y * 32;
    int tx = threadIdx.x, ty = threadIdx.y; // 32x8
    #pragma unroll
    for (int r = ty; r < 32; r += 8)
        tile[r][tx] = in[((size_t)c * DIM + ch0 + r) * (HF * WF) + p0 + tx];
    __syncthreads();
    #pragma unroll
    for (int r = ty; r < 32; r += 8)
        g_feats[((size_t)c * (HF * WF) + p0 + r) * DIM + ch0 + tx] = tile[tx][r];
}

// ---------------- mask dtype detection ----------------
__global__ void detect_mask(const unsigned char* __restrict__ m, int nbytes) {
    __shared__ int ge2, odd1;
    if (threadIdx.x == 0) { ge2 = 0; odd1 = 0; }
    __syncthreads();
    for (int i = threadIdx.x; i < nbytes; i += blockDim.x) {
        unsigned char v = m[i];
        if (v >= 2) atomicOr(&ge2, 1);
        if (v == 1 && (i & 3)) atomicOr(&odd1, 1);
    }
    __syncthreads();
    if (threadIdx.x == 0) g_mask_mode = ge2 ? 2 : (odd1 ? 0 : 1);
}

// ---------------- bilinear gather (channel-per-lane) ----------------
__device__ __forceinline__ float bilin(const float* __restrict__ src, int rstride,
                                       int H, int W, float lx, float ly) {
    float ix = lx * W - 0.5f, iy = ly * H - 0.5f;
    float x0f = floorf(ix), y0f = floorf(iy);
    float wx = ix - x0f, wy = iy - y0f;
    int x0 = (int)x0f, y0 = (int)y0f, x1 = x0 + 1, y1 = y0 + 1;
    bool vx0 = (x0 >= 0) & (x0 < W), vx1 = (x1 >= 0) & (x1 < W);
    bool vy0 = (y0 >= 0) & (y0 < H), vy1 = (y1 >= 0) & (y1 < H);
    float v = 0.f;
    if (vy0) {
        if (vx0) v += (1.f - wx) * (1.f - wy) * __ldg(src + ((size_t)y0 * W + x0) * rstride);
        if (vx1) v += wx * (1.f - wy) * __ldg(src + ((size_t)y0 * W + x1) * rstride);
    }
    if (vy1) {
        if (vx0) v += (1.f - wx) * wy * __ldg(src + ((size_t)y1 * W + x0) * rstride);
        if (vx1) v += wx * wy * __ldg(src + ((size_t)y1 * W + x1) * rstride);
    }
    return v;
}

// ---------------- temporal deformable sampling ----------------
__global__ void temporal_kernel(const float* __restrict__ ref2d, const float* __restrict__ ego) {
    int n = blockIdx.x;
    int head = threadIdx.x >> 5, lane = threadIdx.x & 31;
    float rx = __ldg(ref2d + (size_t)n * 2 + 0);
    float ry = __ldg(ref2d + (size_t)n * 2 + 1);
    float acc = 0.f;
    #pragma unroll
    for (int si = 0; si < 2; si++) {
        float l[PT], mx = -1e30f, se = 0.f;
        #pragma unroll
        for (int pt = 0; pt < PT; pt++) {
            l[pt] = g_twl[(size_t)n * 64 + si * 32 + head * 4 + pt];
            mx = fmaxf(mx, l[pt]);
        }
        #pragma unroll
        for (int pt = 0; pt < PT; pt++) { l[pt] = __expf(l[pt] - mx); se += l[pt]; }
        float inv = 1.f / se;
        float bx = rx + (si == 0 ? __ldg(ego + 0) : 0.f);
        float by = ry + (si == 0 ? __ldg(ego + 1) : 0.f);
        const float* src = g_ai + (si == 0 ? 0 : 256) + head * 32 + lane; // row stride 512
        #pragma unroll
        for (int pt = 0; pt < PT; pt++) {
            float ox = tanhf(g_toff[(size_t)n * 128 + si * 64 + head * 8 + pt * 2 + 0]) * T_RAD;
            float oy = tanhf(g_toff[(size_t)n * 128 + si * 64 + head * 8 + pt * 2 + 1]) * T_RAD;
            acc += l[pt] * inv * bilin(src, 512, BHH, BWW, bx + ox, by + oy);
        }
    }
    g_tfused[(size_t)n * DIM + head * 32 + lane] = acc * 0.5f;
}

// ---------------- spatial deformable cross-attention ----------------
__global__ void spatial_kernel(const float* __restrict__ refcam,
                               const unsigned char* __restrict__ mask) {
    int n = blockIdx.x;
    int head = threadIdx.x >> 5, lane = threadIdx.x & 31;
    int mode = g_mask_mode;
    float acc = 0.f;
    int cnt = 0;
    for (int c = 0; c < NC; c++) {
        bool vis[PP];
        bool any = false;
        #pragma unroll
        for (int pp = 0; pp < PP; pp++) {
            size_t mi = ((size_t)c * NQ + n) * PP + pp;
            bool v;
            if (mode == 0)      v = mask[mi] != 0;
            else if (mode == 1) v = ((const int*)mask)[mi] != 0;
            else                v = ((const float*)mask)[mi] != 0.f;
            vis[pp] = v;
            any |= v;
        }
        if (!any) continue;
        cnt++;
        float e[16];
        float mx = -1e30f, se = 0.f;
        #pragma unroll
        for (int p = 0; p < 16; p++) {
            if (vis[p >> 2]) {
                e[p] = g_swl[(size_t)n * 128 + head * 16 + p];
                mx = fmaxf(mx, e[p]);
            } else e[p] = -1e30f;
        }
        #pragma unroll
        for (int p = 0; p < 16; p++) {
            e[p] = vis[p >> 2] ? __expf(e[p] - mx) : 0.f;
            se += e[p];
        }
        float inv = 1.f / se;
        const float* src = g_feats + (size_t)c * (HF * WF * DIM) + head * 32 + lane;
        #pragma unroll
        for (int p = 0; p < 16; p++) {
            if (!vis[p >> 2]) continue;
            int pp = p >> 2;
            float lx = __ldg(refcam + (((size_t)c * NQ + n) * PP + pp) * 2 + 0)
                     + tanhf(g_soff[(size_t)n * 256 + head * 32 + p * 2 + 0]) * S_RAD;
            float ly = __ldg(refcam + (((size_t)c * NQ + n) * PP + pp) * 2 + 1)
                     + tanhf(g_soff[(size_t)n * 256 + head * 32 + p * 2 + 1]) * S_RAD;
            acc += e[p] * inv * bilin(src, DIM, HF, WF, lx, ly);
        }
    }
    g_sfused[(size_t)n * DIM + head * 32 + lane] = acc / (float)(cnt > 0 ? cnt : 1);
}

// ---------------- SGEMM (double-buffered, templated tiles) ----------------
// C[M,N] = A[M,K] @ B[K,N] + bias (+res) (relu?)
// 256 threads. BK=16. Register-prefetch double buffering.
template<int BM, int BN>
__global__ __launch_bounds__(256, 2)
void sgemm_db(const float* __restrict__ A, const float* __restrict__ B,
              const float* __restrict__ bias, const float* __restrict__ res,
              float* __restrict__ C, int M, int N, int K, int relu) {
    constexpr int BK = 16;
    constexpr int TM = (BM == 128) ? 8 : 4;
    constexpr int TN = (BN == 128) ? 8 : 4;
    constexpr int AF4 = BM * BK / 4 / 256;   // float4 per thread for A tile
    constexpr int BF4 = BK * BN / 4 / 256;   // float4 per thread for B tile

    __shared__ __align__(16) float As[2][BK][BM];
    __shared__ __align__(16) float Bs[2][BK][BN];

    int tid = threadIdx.x;
    int bm = blockIdx.y * BM;
    int bn = blockIdx.x * BN;
    int tx = tid & 15, ty = tid >> 4; // 16x16 thread grid

    float4 pa[AF4], pb[BF4];

    float acc[TM][TN];
    #pragma unroll
    for (int i = 0; i < TM; i++)
        #pragma unroll
        for (int j = 0; j < TN; j++) acc[i][j] = 0.f;

    // ---- prologue: load tile 0 ----
    #pragma unroll
    for (int t = 0; t < AF4; t++) {
        int f = tid + t * 256;
        int row = f / (BK / 4), cq = f % (BK / 4);
        pa[t] = make_float4(0.f, 0.f, 0.f, 0.f);
        if (bm + row < M) pa[t] = *(const float4*)(A + (size_t)(bm + row) * K + cq * 4);
    }
    #pragma unroll
    for (int t = 0; t < BF4; t++) {
        int f = tid + t * 256;
        int row = f / (BN / 4), cq = f % (BN / 4);
        pb[t] = make_float4(0.f, 0.f, 0.f, 0.f);
        if (bn + cq * 4 < N) pb[t] = *(const float4*)(B + (size_t)row * N + bn + cq * 4);
    }
    #pragma unroll
    for (int t = 0; t < AF4; t++) {
        int f = tid + t * 256;
        int row = f / (BK / 4), cq = f % (BK / 4);
        As[0][cq * 4 + 0][row] = pa[t].x;
        As[0][cq * 4 + 1][row] = pa[t].y;
        As[0][cq * 4 + 2][row] = pa[t].z;
        As[0][cq * 4 + 3][row] = pa[t].w;
    }
    #pragma unroll
    for (int t = 0; t < BF4; t++) {
        int f = tid + t * 256;
        int row = f / (BN / 4), cq = f % (BN / 4);
        *(float4*)&Bs[0][row][cq * 4] = pb[t];
    }
    __syncthreads();

    int nk = K / BK;
    for (int kt = 0; kt < nk; kt++) {
        int buf = kt & 1;
        // prefetch next tile into registers (hides global latency behind compute)
        if (kt + 1 < nk) {
            int k0 = (kt + 1) * BK;
            #pragma unroll
            for (int t = 0; t < AF4; t++) {
                int f = tid + t * 256;
                int row = f / (BK / 4), cq = f % (BK / 4);
                pa[t] = make_float4(0.f, 0.f, 0.f, 0.f);
                if (bm + row < M) pa[t] = *(const float4*)(A + (size_t)(bm + row) * K + k0 + cq * 4);
            }
            #pragma unroll
            for (int t = 0; t < BF4; t++) {
                int f = tid + t * 256;
                int row = f / (BN / 4), cq = f % (BN / 4);
                pb[t] = make_float4(0.f, 0.f, 0.f, 0.f);
                if (bn + cq * 4 < N) pb[t] = *(const float4*)(B + (size_t)(k0 + row) * N + bn + cq * 4);
            }
        }
        // compute on current buffer
        #pragma unroll
        for (int kk = 0; kk < BK; kk++) {
            float a[TM], b[TN];
            *(float4*)&a[0] = *(const float4*)&As[buf][kk][ty * 4];
            if constexpr (TM == 8) *(float4*)&a[4] = *(const float4*)&As[buf][kk][64 + ty * 4];
            *(float4*)&b[0] = *(const float4*)&Bs[buf][kk][tx * 4];
            if constexpr (TN == 8) *(float4*)&b[4] = *(const float4*)&Bs[buf][kk][64 + tx * 4];
            #pragma unroll
            for (int i = 0; i < TM; i++)
                #pragma unroll
                for (int j = 0; j < TN; j++)
                    acc[i][j] += a[i] * b[j];
        }
        // publish prefetched tile to the other buffer
        if (kt + 1 < nk) {
            __syncthreads();
            int nb = buf ^ 1;
            #pragma unroll
            for (int t = 0; t < AF4; t++) {
                int f = tid + t * 256;
                int row = f / (BK / 4), cq = f % (BK / 4);
                As[nb][cq * 4 + 0][row] = pa[t].x;
                As[nb][cq * 4 + 1][row] = pa[t].y;
                As[nb][cq * 4 + 2][row] = pa[t].z;
                As[nb][cq * 4 + 3][row] = pa[t].w;
            }
            #pragma unroll
            for (int t = 0; t < BF4; t++) {
                int f = tid + t * 256;
                int row = f / (BN / 4), cq = f % (BN / 4);
                *(float4*)&Bs[nb][row][cq * 4] = pb[t];
            }
            __syncthreads();
        }
    }

    // ---- epilogue ----
    #pragma unroll
    for (int i = 0; i < TM; i++) {
        int row;
        if constexpr (TM == 8) row = bm + ((i < 4) ? (ty * 4 + i) : (64 + ty * 4 + i - 4));
        else                   row = bm + ty * 4 + i;
        if (row >= M) continue;
        #pragma unroll
        for (int j = 0; j < TN; j++) {
            int col;
            if constexpr (TN == 8) col = bn + ((j < 4) ? (tx * 4 + j) : (64 + tx * 4 + j - 4));
            else                   col = bn + tx * 4 + j;
            if (col >= N) continue;
            float v = acc[i][j] + __ldg(bias + col);
            if (res) v += res[(size_t)row * N + col];
            if (relu) v = fmaxf(v, 0.f);
            C[(size_t)row * N + col] = v;
        }
    }
}

static inline void sgemm128x128(const float* A, const float* B, const float* bias,
                                const float* res, float* C, int M, int N, int K, int relu) {
    dim3 grid(N / 128, (M + 127) / 128);
    sgemm_db<128, 128><<<grid, 256>>>(A, B, bias, res, C, M, N, K, relu);
}
static inline void sgemm128x64(const float* A, const float* B, const float* bias,
                               const float* res, float* C, int M, int N, int K, int relu) {
    dim3 grid(N / 64, (M + 127) / 128);
    sgemm_db<128, 64><<<grid, 256>>>(A, B, bias, res, C, M, N, K, relu);
}
static inline void sgemm64x64(const float* A, const float* B, const float* bias,
                              const float* res, float* C, int M, int N, int K, int relu) {
    dim3 grid(N / 64, (M + 63) / 64);
    sgemm_db<64, 64><<<grid, 256>>>(A, B, bias, res, C, M, N, K, relu);
}

// ---------------- launch ----------------
extern "C" void kernel_launch(void* const* d_in, const int* in_sizes, int n_in,
                              void* d_out, int out_size) {
    const float* query   = (const float*)d_in[0];
    const float* prevbev = (const float*)d_in[1];
    const float* imfeats = (const float*)d_in[2];
    const float* ref2d   = (const float*)d_in[3];
    const float* refcam  = (const float*)d_in[4];
    const float* ego     = (const float*)d_in[5];
    const float* t_off_w = (const float*)d_in[6];
    const float* t_off_b = (const float*)d_in[7];
    const float* t_wt_w  = (const float*)d_in[8];
    const float* t_wt_b  = (const float*)d_in[9];
    const float* t_out_w = (const float*)d_in[10];
    const float* t_out_b = (const float*)d_in[11];
    const float* s_off_w = (const float*)d_in[12];
    const float* s_off_b = (const float*)d_in[13];
    const float* s_wt_w  = (const float*)d_in[14];
    const float* s_wt_b  = (const float*)d_in[15];
    const float* s_out_w = (const float*)d_in[16];
    const float* s_out_b = (const float*)d_in[17];
    const float* ffn_w1  = (const float*)d_in[18];
    const float* ffn_b1  = (const float*)d_in[19];
    const float* ffn_w2  = (const float*)d_in[20];
    const float* ffn_b2  = (const float*)d_in[21];
    const float* ln1_g   = (const float*)d_in[22];
    const float* ln1_b   = (const float*)d_in[23];
    const float* ln2_g   = (const float*)d_in[24];
    const float* ln2_b   = (const float*)d_in[25];
    const float* ln3_g   = (const float*)d_in[26];
    const float* ln3_b   = (const float*)d_in[27];
    const unsigned char* bev_mask = (const unsigned char*)d_in[28];

    float *ai, *toff, *twl, *tfused, *x, *q2, *soff, *swl, *sfused, *x2, *q3, *h;
    cudaGetSymbolAddress((void**)&ai, g_ai);
    cudaGetSymbolAddress((void**)&toff, g_toff);
    cudaGetSymbolAddress((void**)&twl, g_twl);
    cudaGetSymbolAddress((void**)&tfused, g_tfused);
    cudaGetSymbolAddress((void**)&x, g_x);
    cudaGetSymbolAddress((void**)&q2, g_q2);
    cudaGetSymbolAddress((void**)&soff, g_soff);
    cudaGetSymbolAddress((void**)&swl, g_swl);
    cudaGetSymbolAddress((void**)&sfused, g_sfused);
    cudaGetSymbolAddress((void**)&x2, g_x2);
    cudaGetSymbolAddress((void**)&q3, g_q3);
    cudaGetSymbolAddress((void**)&h, g_h);

    // 1) LN(query), LN(prev_bev) -> ai = [pb | q1]   (also the BEV maps, [H,W,C])
    ln1_kernel<<<NQ, 256>>>(query, prevbev, ln1_g, ln1_b);

    // prep: image feature transpose + mask dtype detection (independent)
    transpose_feats<<<dim3(45, 8, NC), dim3(32, 8)>>>(imfeats);
    detect_mask<<<1, 256>>>(bev_mask, NC * NQ * PP);

    // 2) temporal offset / weight projections
    sgemm128x64(ai, t_off_w, t_off_b, nullptr, toff, NQ, 128, 512, 0);   // 158 blocks
    sgemm64x64 (ai, t_wt_w,  t_wt_b,  nullptr, twl,  NQ, 64,  512, 0);   // 157 blocks

    // 3) temporal deformable sampling
    temporal_kernel<<<NQ, 256>>>(ref2d, ego);

    // 4) x = query + tfused @ t_out_w + b
    sgemm128x64(tfused, t_out_w, t_out_b, query, x, NQ, DIM, DIM, 0);    // 316 blocks

    // 5) q2 = LN2(x)
    ln_kernel<<<NQ, 256>>>(x, ln2_g, ln2_b, q2);

    // 6) spatial offset / weight projections
    sgemm128x64(q2, s_off_w, s_off_b, nullptr, soff, NQ, 256, DIM, 0);   // 316 blocks
    sgemm64x64 (q2, s_wt_w,  s_wt_b,  nullptr, swl,  NQ, 128, DIM, 0);   // 314 blocks

    // 7) spatial deformable cross-attention over 6 cameras
    spatial_kernel<<<NQ, 256>>>(refcam, bev_mask);

    // 8) x2 = x + sfused @ s_out_w + b
    sgemm128x64(sfused, s_out_w, s_out_b, x, x2, NQ, DIM, DIM, 0);       // 316 blocks

    // 9) q3 = LN3(x2); h = relu(q3 @ ffn_w1 + b1); out = x2 + h @ ffn_w2 + b2
    ln_kernel<<<NQ, 256>>>(x2, ln3_g, ln3_b, q3);
    sgemm128x128(q3, ffn_w1, ffn_b1, nullptr, h, NQ, DFF, DIM, 1);       // 632 blocks
    sgemm128x64 (h, ffn_w2, ffn_b2, x2, (float*)d_out, NQ, DIM, DFF, 0); // 316 blocks
}

// round 4
// speedup vs baseline: 1.2940x; 1.2513x over previous
#include <cuda_runtime.h>
#include <math.h>

// ---------------- problem constants ----------------
#define NQ   10000
#define DIM  256
#define NH   8
#define HD   32
#define PT   4
#define PP   4
#define PSS  4
#define NC   6
#define HF   24
#define WF   60
#define BHH  100
#define BWW  100
#define DFF  1024
#define T_RAD 0.15f
#define S_RAD 0.12f

// ---------------- scratch (device globals; no allocation allowed) ----------
__device__ __align__(256) float g_ai[NQ * 512];        // [pb(256) | q1(256)] per row
__device__ __align__(256) float g_toff[NQ * 128];      // raw temporal offsets
__device__ __align__(256) float g_twl[NQ * 64];        // temporal weight logits
__device__ __align__(256) float g_tfused[NQ * DIM];
__device__ __align__(256) float g_x[NQ * DIM];
__device__ __align__(256) float g_q2[NQ * DIM];
__device__ __align__(256) float g_soff[NQ * 256];      // raw spatial offsets
__device__ __align__(256) float g_swl[NQ * 128];       // spatial weight logits
__device__ __align__(256) float g_sfused[NQ * DIM];
__device__ __align__(256) float g_x2[NQ * DIM];
__device__ __align__(256) float g_q3[NQ * DIM];
__device__ __align__(256) float g_h[NQ * DFF];
__device__ __align__(256) float g_feats[NC * HF * WF * DIM]; // [NC][H*W][256]
__device__ int g_mask_mode; // 0=u8, 1=i32, 2=f32

// ---------------- reductions ----------------
__device__ __forceinline__ float blockSum256(float v, float* sm) {
    #pragma unroll
    for (int o = 16; o > 0; o >>= 1) v += __shfl_down_sync(0xffffffffu, v, o);
    int w = threadIdx.x >> 5;
    if ((threadIdx.x & 31) == 0) sm[w] = v;
    __syncthreads();
    if (threadIdx.x < 32) {
        float x = (threadIdx.x < 8) ? sm[threadIdx.x] : 0.f;
        #pragma unroll
        for (int o = 4; o > 0; o >>= 1) x += __shfl_down_sync(0xffffffffu, x, o);
        if (threadIdx.x == 0) sm[0] = x;
    }
    __syncthreads();
    float r = sm[0];
    __syncthreads();
    return r;
}

// ---------------- layernorm kernels ----------------
__global__ void ln1_kernel(const float* __restrict__ q, const float* __restrict__ p,
                           const float* __restrict__ g, const float* __restrict__ b) {
    int n = blockIdx.x, t = threadIdx.x;
    __shared__ float sm[8];
    float gv = g[t], bv = b[t];
    float vq = q[(size_t)n * DIM + t];
    float vp = p[(size_t)n * DIM + t];
    float muq = blockSum256(vq, sm) * (1.f / DIM);
    float dq = vq - muq;
    float varq = blockSum256(dq * dq, sm) * (1.f / DIM);
    float mup = blockSum256(vp, sm) * (1.f / DIM);
    float dp = vp - mup;
    float varp = blockSum256(dp * dp, sm) * (1.f / DIM);
    g_ai[(size_t)n * 512 + t]       = dp * rsqrtf(varp + 1e-5f) * gv + bv; // pb
    g_ai[(size_t)n * 512 + 256 + t] = dq * rsqrtf(varq + 1e-5f) * gv + bv; // q1
}

__global__ void ln_kernel(const float* __restrict__ in, const float* __restrict__ g,
                          const float* __restrict__ b, float* __restrict__ out) {
    int n = blockIdx.x, t = threadIdx.x;
    __shared__ float sm[8];
    float v = in[(size_t)n * DIM + t];
    float mu = blockSum256(v, sm) * (1.f / DIM);
    float d = v - mu;
    float var = blockSum256(d * d, sm) * (1.f / DIM);
    out[(size_t)n * DIM + t] = d * rsqrtf(var + 1e-5f) * g[t] + b[t];
}

// ---------------- feature transpose [NC][256][1440] -> [NC][1440][256] ----
__global__ void transpose_feats(const float* __restrict__ in) {
    __shared__ float tile[32][33];
    int c = blockIdx.z;
    int p0 = blockIdx.x * 32, ch0 = blockIdx.y * 32;
    int tx = threadIdx.x, ty = threadIdx.y; // 32x8
    #pragma unroll
    for (int r = ty; r < 32; r += 8)
        tile[r][tx] = in[((size_t)c * DIM + ch0 + r) * (HF * WF) + p0 + tx];
    __syncthreads();
    #pragma unroll
    for (int r = ty; r < 32; r += 8)
        g_feats[((size_t)c * (HF * WF) + p0 + r) * DIM + ch0 + tx] = tile[tx][r];
}

// ---------------- mask dtype detection ----------------
__global__ void detect_mask(const unsigned char* __restrict__ m, int nbytes) {
    __shared__ int ge2, odd1;
    if (threadIdx.x == 0) { ge2 = 0; odd1 = 0; }
    __syncthreads();
    for (int i = threadIdx.x; i < nbytes; i += blockDim.x) {
        unsigned char v = m[i];
        if (v >= 2) atomicOr(&ge2, 1);
        if (v == 1 && (i & 3)) atomicOr(&odd1, 1);
    }
    __syncthreads();
    if (threadIdx.x == 0) g_mask_mode = ge2 ? 2 : (odd1 ? 0 : 1);
}

// ---------------- bilinear gather (channel-per-lane) ----------------
__device__ __forceinline__ float bilin(const float* __restrict__ src, int rstride,
                                       int H, int W, float lx, float ly) {
    float ix = lx * W - 0.5f, iy = ly * H - 0.5f;
    float x0f = floorf(ix), y0f = floorf(iy);
    float wx = ix - x0f, wy = iy - y0f;
    int x0 = (int)x0f, y0 = (int)y0f, x1 = x0 + 1, y1 = y0 + 1;
    bool vx0 = (x0 >= 0) & (x0 < W), vx1 = (x1 >= 0) & (x1 < W);
    bool vy0 = (y0 >= 0) & (y0 < H), vy1 = (y1 >= 0) & (y1 < H);
    float v = 0.f;
    if (vy0) {
        if (vx0) v += (1.f - wx) * (1.f - wy) * __ldg(src + ((size_t)y0 * W + x0) * rstride);
        if (vx1) v += wx * (1.f - wy) * __ldg(src + ((size_t)y0 * W + x1) * rstride);
    }
    if (vy1) {
        if (vx0) v += (1.f - wx) * wy * __ldg(src + ((size_t)y1 * W + x0) * rstride);
        if (vx1) v += wx * wy * __ldg(src + ((size_t)y1 * W + x1) * rstride);
    }
    return v;
}

// ---------------- temporal deformable sampling ----------------
__global__ void temporal_kernel(const float* __restrict__ ref2d, const float* __restrict__ ego) {
    int n = blockIdx.x;
    int head = threadIdx.x >> 5, lane = threadIdx.x & 31;
    float rx = __ldg(ref2d + (size_t)n * 2 + 0);
    float ry = __ldg(ref2d + (size_t)n * 2 + 1);
    float acc = 0.f;
    #pragma unroll
    for (int si = 0; si < 2; si++) {
        float l[PT], mx = -1e30f, se = 0.f;
        #pragma unroll
        for (int pt = 0; pt < PT; pt++) {
            l[pt] = g_twl[(size_t)n * 64 + si * 32 + head * 4 + pt];
            mx = fmaxf(mx, l[pt]);
        }
        #pragma unroll
        for (int pt = 0; pt < PT; pt++) { l[pt] = __expf(l[pt] - mx); se += l[pt]; }
        float inv = 1.f / se;
        float bx = rx + (si == 0 ? __ldg(ego + 0) : 0.f);
        float by = ry + (si == 0 ? __ldg(ego + 1) : 0.f);
        const float* src = g_ai + (si == 0 ? 0 : 256) + head * 32 + lane; // row stride 512
        #pragma unroll
        for (int pt = 0; pt < PT; pt++) {
            float ox = tanhf(g_toff[(size_t)n * 128 + si * 64 + head * 8 + pt * 2 + 0]) * T_RAD;
            float oy = tanhf(g_toff[(size_t)n * 128 + si * 64 + head * 8 + pt * 2 + 1]) * T_RAD;
            acc += l[pt] * inv * bilin(src, 512, BHH, BWW, bx + ox, by + oy);
        }
    }
    g_tfused[(size_t)n * DIM + head * 32 + lane] = acc * 0.5f;
}

// ---------------- spatial deformable cross-attention ----------------
__global__ void spatial_kernel(const float* __restrict__ refcam,
                               const unsigned char* __restrict__ mask) {
    int n = blockIdx.x;
    int head = threadIdx.x >> 5, lane = threadIdx.x & 31;
    int mode = g_mask_mode;
    float acc = 0.f;
    int cnt = 0;
    for (int c = 0; c < NC; c++) {
        bool vis[PP];
        bool any = false;
        #pragma unroll
        for (int pp = 0; pp < PP; pp++) {
            size_t mi = ((size_t)c * NQ + n) * PP + pp;
            bool v;
            if (mode == 0)      v = mask[mi] != 0;
            else if (mode == 1) v = ((const int*)mask)[mi] != 0;
            else                v = ((const float*)mask)[mi] != 0.f;
            vis[pp] = v;
            any |= v;
        }
        if (!any) continue;
        cnt++;
        float e[16];
        float mx = -1e30f, se = 0.f;
        #pragma unroll
        for (int p = 0; p < 16; p++) {
            if (vis[p >> 2]) {
                e[p] = g_swl[(size_t)n * 128 + head * 16 + p];
                mx = fmaxf(mx, e[p]);
            } else e[p] = -1e30f;
        }
        #pragma unroll
        for (int p = 0; p < 16; p++) {
            e[p] = vis[p >> 2] ? __expf(e[p] - mx) : 0.f;
            se += e[p];
        }
        float inv = 1.f / se;
        const float* src = g_feats + (size_t)c * (HF * WF * DIM) + head * 32 + lane;
        #pragma unroll
        for (int p = 0; p < 16; p++) {
            if (!vis[p >> 2]) continue;
            int pp = p >> 2;
            float lx = __ldg(refcam + (((size_t)c * NQ + n) * PP + pp) * 2 + 0)
                     + tanhf(g_soff[(size_t)n * 256 + head * 32 + p * 2 + 0]) * S_RAD;
            float ly = __ldg(refcam + (((size_t)c * NQ + n) * PP + pp) * 2 + 1)
                     + tanhf(g_soff[(size_t)n * 256 + head * 32 + p * 2 + 1]) * S_RAD;
            acc += e[p] * inv * bilin(src, DIM, HF, WF, lx, ly);
        }
    }
    g_sfused[(size_t)n * DIM + head * 32 + lane] = acc / (float)(cnt > 0 ? cnt : 1);
}

// ---------------- TF32 tensor-core GEMM -----------------------------------
// C[M,N] = A[M,K] @ B[K,N] + bias (+res) (relu?)   via mma.sync m16n8k8 tf32
// BM=128, BN=128, BK=16. 256 threads = 8 warps (4 m-warps x 2 n-warps),
// each warp owns a 32x64 tile = 2 x 8 mma tiles. fp32 accumulate.
// Inputs rounded to tf32 with cvt.rna at the smem-fill stage (unbiased).
__device__ __forceinline__ unsigned f2tf(float x) {
    unsigned r;
    asm("cvt.rna.tf32.f32 %0, %1;" : "=r"(r) : "f"(x));
    return r;
}

#define AS_STRIDE 20    // 16 + 4 pad -> conflict-free fragment loads
#define BS_STRIDE 132   // 128 + 4 pad

__global__ __launch_bounds__(256, 2)
void tgemm(const float* __restrict__ A, const float* __restrict__ B,
           const float* __restrict__ bias, const float* __restrict__ res,
           float* __restrict__ C, int M, int N, int K, int relu) {
    __shared__ __align__(16) unsigned As[2][128 * AS_STRIDE];
    __shared__ __align__(16) unsigned Bs[2][16 * BS_STRIDE];

    int tid = threadIdx.x;
    int lane = tid & 31, wid = tid >> 5;
    int warp_m = wid & 3;        // 4 warps x 32 rows
    int warp_n = wid >> 2;       // 2 warps x 64 cols
    int lr = lane >> 2;          // 0..7
    int lc = lane & 3;           // 0..3
    int bm = blockIdx.y * 128;
    int bn = blockIdx.x * 128;

    // global load indexing: A tile 128x16 -> 512 float4 (2/thread, 4 f4/row)
    int a_row = tid >> 2, a_c4 = (tid & 3);          // +t*256 -> rows 0..63 / 64..127
    // B tile 16x128 -> 512 float4 (2/thread, 32 f4/row)
    int b_row = tid >> 5, b_c4 = tid & 31;           // +t*256 -> rows 0..7 / 8..15

    float4 pa[2], pb[2];

    float acc[2][8][4];
    #pragma unroll
    for (int mt = 0; mt < 2; mt++)
        #pragma unroll
        for (int nt = 0; nt < 8; nt++)
            #pragma unroll
            for (int r = 0; r < 4; r++) acc[mt][nt][r] = 0.f;

    // ---- prologue: global-load tile 0 ----
    #pragma unroll
    for (int t = 0; t < 2; t++) {
        int row = a_row + t * 64;
        pa[t] = make_float4(0.f, 0.f, 0.f, 0.f);
        if (bm + row < M) pa[t] = *(const float4*)(A + (size_t)(bm + row) * K + a_c4 * 4);
        int brow = b_row + t * 8;
        pb[t] = make_float4(0.f, 0.f, 0.f, 0.f);
        if (bn + b_c4 * 4 < N) pb[t] = *(const float4*)(B + (size_t)brow * N + bn + b_c4 * 4);
    }
    #pragma unroll
    for (int t = 0; t < 2; t++) {
        unsigned* d = &As[0][(a_row + t * 64) * AS_STRIDE + a_c4 * 4];
        d[0] = f2tf(pa[t].x); d[1] = f2tf(pa[t].y); d[2] = f2tf(pa[t].z); d[3] = f2tf(pa[t].w);
        unsigned* e = &Bs[0][(b_row + t * 8) * BS_STRIDE + b_c4 * 4];
        e[0] = f2tf(pb[t].x); e[1] = f2tf(pb[t].y); e[2] = f2tf(pb[t].z); e[3] = f2tf(pb[t].w);
    }
    __syncthreads();

    int nk = K >> 4;
    for (int kt = 0; kt < nk; kt++) {
        int buf = kt & 1;
        if (kt + 1 < nk) {
            int k0 = (kt + 1) << 4;
            #pragma unroll
            for (int t = 0; t < 2; t++) {
                int row = a_row + t * 64;
                pa[t] = make_float4(0.f, 0.f, 0.f, 0.f);
                if (bm + row < M) pa[t] = *(const float4*)(A + (size_t)(bm + row) * K + k0 + a_c4 * 4);
                int brow = b_row + t * 8;
                pb[t] = make_float4(0.f, 0.f, 0.f, 0.f);
                if (bn + b_c4 * 4 < N) pb[t] = *(const float4*)(B + (size_t)(k0 + brow) * N + bn + b_c4 * 4);
            }
        }
        // ---- compute: 2 k8-steps on current buffer ----
        #pragma unroll
        for (int kk = 0; kk < 2; kk++) {
            unsigned afr[2][4];
            #pragma unroll
            for (int mt = 0; mt < 2; mt++) {
                int r0 = (warp_m * 32 + mt * 16 + lr) * AS_STRIDE + kk * 8 + lc;
                afr[mt][0] = As[buf][r0];
                afr[mt][1] = As[buf][r0 + 8 * AS_STRIDE];
                afr[mt][2] = As[buf][r0 + 4];
                afr[mt][3] = As[buf][r0 + 8 * AS_STRIDE + 4];
            }
            #pragma unroll
            for (int nt = 0; nt < 8; nt++) {
                int cb = warp_n * 64 + nt * 8 + lr;
                unsigned b0 = Bs[buf][(kk * 8 + lc) * BS_STRIDE + cb];
                unsigned b1 = Bs[buf][(kk * 8 + 4 + lc) * BS_STRIDE + cb];
                #pragma unroll
                for (int mt = 0; mt < 2; mt++) {
                    asm volatile(
                        "mma.sync.aligned.m16n8k8.row.col.f32.tf32.tf32.f32 "
                        "{%0,%1,%2,%3}, {%4,%5,%6,%7}, {%8,%9}, {%0,%1,%2,%3};"
                        : "+f"(acc[mt][nt][0]), "+f"(acc[mt][nt][1]),
                          "+f"(acc[mt][nt][2]), "+f"(acc[mt][nt][3])
                        : "r"(afr[mt][0]), "r"(afr[mt][1]), "r"(afr[mt][2]), "r"(afr[mt][3]),
                          "r"(b0), "r"(b1));
                }
            }
        }
        // ---- publish prefetched tile ----
        if (kt + 1 < nk) {
            __syncthreads();
            int nb = buf ^ 1;
            #pragma unroll
            for (int t = 0; t < 2; t++) {
                unsigned* d = &As[nb][(a_row + t * 64) * AS_STRIDE + a_c4 * 4];
                d[0] = f2tf(pa[t].x); d[1] = f2tf(pa[t].y); d[2] = f2tf(pa[t].z); d[3] = f2tf(pa[t].w);
                unsigned* e = &Bs[nb][(b_row + t * 8) * BS_STRIDE + b_c4 * 4];
                e[0] = f2tf(pb[t].x); e[1] = f2tf(pb[t].y); e[2] = f2tf(pb[t].z); e[3] = f2tf(pb[t].w);
            }
            __syncthreads();
        }
    }

    // ---- epilogue ----
    #pragma unroll
    for (int mt = 0; mt < 2; mt++) {
        #pragma unroll
        for (int nt = 0; nt < 8; nt++) {
            int r0 = bm + warp_m * 32 + mt * 16 + lr;
            int c0 = bn + warp_n * 64 + nt * 8 + lc * 2;
            #pragma unroll
            for (int half = 0; half < 2; half++) {
                int row = r0 + half * 8;
                if (row >= M) continue;
                #pragma unroll
                for (int j = 0; j < 2; j++) {
                    int col = c0 + j;
                    if (col >= N) continue;
                    float v = acc[mt][nt][half * 2 + j] + __ldg(bias + col);
                    if (res) v += res[(size_t)row * N + col];
                    if (relu) v = fmaxf(v, 0.f);
                    C[(size_t)row * N + col] = v;
                }
            }
        }
    }
}

static inline void gemm(const float* A, const float* B, const float* bias, const float* res,
                        float* C, int M, int N, int K, int relu) {
    dim3 grid((N + 127) / 128, (M + 127) / 128);
    tgemm<<<grid, 256>>>(A, B, bias, res, C, M, N, K, relu);
}

// ---------------- launch ----------------
extern "C" void kernel_launch(void* const* d_in, const int* in_sizes, int n_in,
                              void* d_out, int out_size) {
    const float* query   = (const float*)d_in[0];
    const float* prevbev = (const float*)d_in[1];
    const float* imfeats = (const float*)d_in[2];
    const float* ref2d   = (const float*)d_in[3];
    const float* refcam  = (const float*)d_in[4];
    const float* ego     = (const float*)d_in[5];
    const float* t_off_w = (const float*)d_in[6];
    const float* t_off_b = (const float*)d_in[7];
    const float* t_wt_w  = (const float*)d_in[8];
    const float* t_wt_b  = (const float*)d_in[9];
    const float* t_out_w = (const float*)d_in[10];
    const float* t_out_b = (const float*)d_in[11];
    const float* s_off_w = (const float*)d_in[12];
    const float* s_off_b = (const float*)d_in[13];
    const float* s_wt_w  = (const float*)d_in[14];
    const float* s_wt_b  = (const float*)d_in[15];
    const float* s_out_w = (const float*)d_in[16];
    const float* s_out_b = (const float*)d_in[17];
    const float* ffn_w1  = (const float*)d_in[18];
    const float* ffn_b1  = (const float*)d_in[19];
    const float* ffn_w2  = (const float*)d_in[20];
    const float* ffn_b2  = (const float*)d_in[21];
    const float* ln1_g   = (const float*)d_in[22];
    const float* ln1_b   = (const float*)d_in[23];
    const float* ln2_g   = (const float*)d_in[24];
    const float* ln2_b   = (const float*)d_in[25];
    const float* ln3_g   = (const float*)d_in[26];
    const float* ln3_b   = (const float*)d_in[27];
    const unsigned char* bev_mask = (const unsigned char*)d_in[28];

    float *ai, *toff, *twl, *tfused, *x, *q2, *soff, *swl, *sfused, *x2, *q3, *h;
    cudaGetSymbolAddress((void**)&ai, g_ai);
    cudaGetSymbolAddress((void**)&toff, g_toff);
    cudaGetSymbolAddress((void**)&twl, g_twl);
    cudaGetSymbolAddress((void**)&tfused, g_tfused);
    cudaGetSymbolAddress((void**)&x, g_x);
    cudaGetSymbolAddress((void**)&q2, g_q2);
    cudaGetSymbolAddress((void**)&soff, g_soff);
    cudaGetSymbolAddress((void**)&swl, g_swl);
    cudaGetSymbolAddress((void**)&sfused, g_sfused);
    cudaGetSymbolAddress((void**)&x2, g_x2);
    cudaGetSymbolAddress((void**)&q3, g_q3);
    cudaGetSymbolAddress((void**)&h, g_h);

    // 1) LN(query), LN(prev_bev) -> ai = [pb | q1]   (also the BEV maps, [H,W,C])
    ln1_kernel<<<NQ, 256>>>(query, prevbev, ln1_g, ln1_b);

    // prep: image feature transpose + mask dtype detection (independent)
    transpose_feats<<<dim3(45, 8, NC), dim3(32, 8)>>>(imfeats);
    detect_mask<<<1, 256>>>(bev_mask, NC * NQ * PP);

    // 2) temporal offset / weight projections
    gemm(ai, t_off_w, t_off_b, nullptr, toff, NQ, 128, 512, 0);
    gemm(ai, t_wt_w,  t_wt_b,  nullptr, twl,  NQ, 64,  512, 0);

    // 3) temporal deformable sampling
    temporal_kernel<<<NQ, 256>>>(ref2d, ego);

    // 4) x = query + tfused @ t_out_w + b
    gemm(tfused, t_out_w, t_out_b, query, x, NQ, DIM, DIM, 0);

    // 5) q2 = LN2(x)
    ln_kernel<<<NQ, 256>>>(x, ln2_g, ln2_b, q2);

    // 6) spatial offset / weight projections
    gemm(q2, s_off_w, s_off_b, nullptr, soff, NQ, 256, DIM, 0);
    gemm(q2, s_wt_w,  s_wt_b,  nullptr, swl,  NQ, 128, DIM, 0);

    // 7) spatial deformable cross-attention over 6 cameras
    spatial_kernel<<<NQ, 256>>>(refcam, bev_mask);

    // 8) x2 = x + sfused @ s_out_w + b
    gemm(sfused, s_out_w, s_out_b, x, x2, NQ, DIM, DIM, 0);

    // 9) q3 = LN3(x2); h = relu(q3 @ ffn_w1 + b1); out = x2 + h @ ffn_w2 + b2
    ln_kernel<<<NQ, 256>>>(x2, ln3_g, ln3_b, q3);
    gemm(q3, ffn_w1, ffn_b1, nullptr, h, NQ, DFF, DIM, 1);
    gemm(h, ffn_w2, ffn_b2, x2, (float*)d_out, NQ, DIM, DFF, 0);
}

// round 6
// speedup vs baseline: 1.3432x; 1.0380x over previous
#include <cuda_runtime.h>
#include <cuda_fp16.h>
#include <math.h>

// ---------------- problem constants ----------------
#define NQ   10000
#define DIM  256
#define NH   8
#define HD   32
#define PT   4
#define PP   4
#define PSS  4
#define NC   6
#define HF   24
#define WF   60
#define BHH  100
#define BWW  100
#define DFF  1024
#define T_RAD 0.15f
#define S_RAD 0.12f

// ---------------- scratch (device globals; no allocation allowed) ----------
__device__ __align__(256) float g_ai[NQ * 512];        // [pb(256) | q1(256)] per row
__device__ __align__(256) float g_toff[NQ * 128];      // tanh-scaled temporal offsets
__device__ __align__(256) float g_twl[NQ * 64];        // temporal weight logits
__device__ __align__(256) float g_tfused[NQ * DIM];
__device__ __align__(256) float g_x[NQ * DIM];
__device__ __align__(256) float g_q2[NQ * DIM];
__device__ __align__(256) float g_soff[NQ * 256];      // tanh-scaled spatial offsets
__device__ __align__(256) float g_swl[NQ * 128];       // spatial weight logits
__device__ __align__(256) float g_sfused[NQ * DIM];
__device__ __align__(256) float g_x2[NQ * DIM];
__device__ __align__(256) float g_q3[NQ * DIM];
__device__ __align__(256) float g_h[NQ * DFF];
__device__ __align__(256) __half g_feats_h[NC * HF * WF * DIM]; // [NC][H*W][256] fp16
__device__ int g_mask_mode; // 0=u8, 1=i32, 2=f32

// ---------------- reductions ----------------
__device__ __forceinline__ float blockSum256(float v, float* sm) {
    #pragma unroll
    for (int o = 16; o > 0; o >>= 1) v += __shfl_down_sync(0xffffffffu, v, o);
    int w = threadIdx.x >> 5;
    if ((threadIdx.x & 31) == 0) sm[w] = v;
    __syncthreads();
    if (threadIdx.x < 32) {
        float x = (threadIdx.x < 8) ? sm[threadIdx.x] : 0.f;
        #pragma unroll
        for (int o = 4; o > 0; o >>= 1) x += __shfl_down_sync(0xffffffffu, x, o);
        if (threadIdx.x == 0) sm[0] = x;
    }
    __syncthreads();
    float r = sm[0];
    __syncthreads();
    return r;
}

// ---------------- layernorm kernels ----------------
__global__ void ln1_kernel(const float* __restrict__ q, const float* __restrict__ p,
                           const float* __restrict__ g, const float* __restrict__ b) {
    int n = blockIdx.x, t = threadIdx.x;
    __shared__ float sm[8];
    float gv = g[t], bv = b[t];
    float vq = q[(size_t)n * DIM + t];
    float vp = p[(size_t)n * DIM + t];
    float muq = blockSum256(vq, sm) * (1.f / DIM);
    float dq = vq - muq;
    float varq = blockSum256(dq * dq, sm) * (1.f / DIM);
    float mup = blockSum256(vp, sm) * (1.f / DIM);
    float dp = vp - mup;
    float varp = blockSum256(dp * dp, sm) * (1.f / DIM);
    g_ai[(size_t)n * 512 + t]       = dp * rsqrtf(varp + 1e-5f) * gv + bv; // pb
    g_ai[(size_t)n * 512 + 256 + t] = dq * rsqrtf(varq + 1e-5f) * gv + bv; // q1
}

__global__ void ln_kernel(const float* __restrict__ in, const float* __restrict__ g,
                          const float* __restrict__ b, float* __restrict__ out) {
    int n = blockIdx.x, t = threadIdx.x;
    __shared__ float sm[8];
    float v = in[(size_t)n * DIM + t];
    float mu = blockSum256(v, sm) * (1.f / DIM);
    float d = v - mu;
    float var = blockSum256(d * d, sm) * (1.f / DIM);
    out[(size_t)n * DIM + t] = d * rsqrtf(var + 1e-5f) * g[t] + b[t];
}

// ---------------- feature transpose [NC][256][1440] -> fp16 [NC][1440][256] -
__global__ void transpose_feats(const float* __restrict__ in) {
    __shared__ float tile[32][33];
    int c = blockIdx.z;
    int p0 = blockIdx.x * 32, ch0 = blockIdx.y * 32;
    int tx = threadIdx.x, ty = threadIdx.y; // 32x8
    #pragma unroll
    for (int r = ty; r < 32; r += 8)
        tile[r][tx] = in[((size_t)c * DIM + ch0 + r) * (HF * WF) + p0 + tx];
    __syncthreads();
    #pragma unroll
    for (int r = ty; r < 32; r += 8)
        g_feats_h[((size_t)c * (HF * WF) + p0 + r) * DIM + ch0 + tx] = __float2half(tile[tx][r]);
}

// ---------------- mask dtype detection ----------------
__global__ void detect_mask(const unsigned char* __restrict__ m, int nbytes) {
    __shared__ int ge2, odd1;
    if (threadIdx.x == 0) { ge2 = 0; odd1 = 0; }
    __syncthreads();
    for (int i = threadIdx.x; i < nbytes; i += blockDim.x) {
        unsigned char v = m[i];
        if (v >= 2) atomicOr(&ge2, 1);
        if (v == 1 && (i & 3)) atomicOr(&odd1, 1);
    }
    __syncthreads();
    if (threadIdx.x == 0) g_mask_mode = ge2 ? 2 : (odd1 ? 0 : 1);
}

// ---------------- bilinear gathers (channel-per-lane) ----------------
__device__ __forceinline__ float bilin_f32(const float* __restrict__ src, int rstride,
                                           int H, int W, float lx, float ly) {
    float ix = lx * W - 0.5f, iy = ly * H - 0.5f;
    float x0f = floorf(ix), y0f = floorf(iy);
    float wx = ix - x0f, wy = iy - y0f;
    int x0 = (int)x0f, y0 = (int)y0f, x1 = x0 + 1, y1 = y0 + 1;
    bool vx0 = (x0 >= 0) & (x0 < W), vx1 = (x1 >= 0) & (x1 < W);
    bool vy0 = (y0 >= 0) & (y0 < H), vy1 = (y1 >= 0) & (y1 < H);
    float v = 0.f;
    if (vy0) {
        if (vx0) v += (1.f - wx) * (1.f - wy) * __ldg(src + ((size_t)y0 * W + x0) * rstride);
        if (vx1) v += wx * (1.f - wy) * __ldg(src + ((size_t)y0 * W + x1) * rstride);
    }
    if (vy1) {
        if (vx0) v += (1.f - wx) * wy * __ldg(src + ((size_t)y1 * W + x0) * rstride);
        if (vx1) v += wx * wy * __ldg(src + ((size_t)y1 * W + x1) * rstride);
    }
    return v;
}

__device__ __forceinline__ float bilin_f16(const __half* __restrict__ src,
                                           int H, int W, float lx, float ly) {
    float ix = lx * W - 0.5f, iy = ly * H - 0.5f;
    float x0f = floorf(ix), y0f = floorf(iy);
    float wx = ix - x0f, wy = iy - y0f;
    int x0 = (int)x0f, y0 = (int)y0f, x1 = x0 + 1, y1 = y0 + 1;
    bool vx0 = (x0 >= 0) & (x0 < W), vx1 = (x1 >= 0) & (x1 < W);
    bool vy0 = (y0 >= 0) & (y0 < H), vy1 = (y1 >= 0) & (y1 < H);
    float v = 0.f;
    if (vy0) {
        if (vx0) v += (1.f - wx) * (1.f - wy) * __half2float(__ldg(src + ((size_t)y0 * W + x0) * DIM));
        if (vx1) v += wx * (1.f - wy) * __half2float(__ldg(src + ((size_t)y0 * W + x1) * DIM));
    }
    if (vy1) {
        if (vx0) v += (1.f - wx) * wy * __half2float(__ldg(src + ((size_t)y1 * W + x0) * DIM));
        if (vx1) v += wx * wy * __half2float(__ldg(src + ((size_t)y1 * W + x1) * DIM));
    }
    return v;
}

// ---------------- temporal deformable sampling ----------------
__global__ void temporal_kernel(const float* __restrict__ ref2d, const float* __restrict__ ego) {
    int n = blockIdx.x;
    int head = threadIdx.x >> 5, lane = threadIdx.x & 31;
    float rx = __ldg(ref2d + (size_t)n * 2 + 0);
    float ry = __ldg(ref2d + (size_t)n * 2 + 1);
    float acc = 0.f;
    #pragma unroll
    for (int si = 0; si < 2; si++) {
        float l[PT], mx = -1e30f, se = 0.f;
        #pragma unroll
        for (int pt = 0; pt < PT; pt++) {
            l[pt] = g_twl[(size_t)n * 64 + si * 32 + head * 4 + pt];
            mx = fmaxf(mx, l[pt]);
        }
        #pragma unroll
        for (int pt = 0; pt < PT; pt++) { l[pt] = __expf(l[pt] - mx); se += l[pt]; }
        float inv = 1.f / se;
        float bx = rx + (si == 0 ? __ldg(ego + 0) : 0.f);
        float by = ry + (si == 0 ? __ldg(ego + 1) : 0.f);
        const float* src = g_ai + (si == 0 ? 0 : 256) + head * 32 + lane; // row stride 512
        #pragma unroll
        for (int pt = 0; pt < PT; pt++) {
            float ox = g_toff[(size_t)n * 128 + si * 64 + head * 8 + pt * 2 + 0];
            float oy = g_toff[(size_t)n * 128 + si * 64 + head * 8 + pt * 2 + 1];
            acc += l[pt] * inv * bilin_f32(src, 512, BHH, BWW, bx + ox, by + oy);
        }
    }
    g_tfused[(size_t)n * DIM + head * 32 + lane] = acc * 0.5f;
}

// ---------------- spatial deformable cross-attention ----------------
__global__ void spatial_kernel(const float* __restrict__ refcam,
                               const unsigned char* __restrict__ mask) {
    int n = blockIdx.x;
    int head = threadIdx.x >> 5, lane = threadIdx.x & 31;
    int mode = g_mask_mode;
    float acc = 0.f;
    int cnt = 0;
    for (int c = 0; c < NC; c++) {
        bool vis[PP];
        bool any = false;
        #pragma unroll
        for (int pp = 0; pp < PP; pp++) {
            size_t mi = ((size_t)c * NQ + n) * PP + pp;
            bool v;
            if (mode == 0)      v = mask[mi] != 0;
            else if (mode == 1) v = ((const int*)mask)[mi] != 0;
            else                v = ((const float*)mask)[mi] != 0.f;
            vis[pp] = v;
            any |= v;
        }
        if (!any) continue;
        cnt++;
        float e[16];
        float mx = -1e30f, se = 0.f;
        #pragma unroll
        for (int p = 0; p < 16; p++) {
            if (vis[p >> 2]) {
                e[p] = g_swl[(size_t)n * 128 + head * 16 + p];
                mx = fmaxf(mx, e[p]);
            } else e[p] = -1e30f;
        }
        #pragma unroll
        for (int p = 0; p < 16; p++) {
            e[p] = vis[p >> 2] ? __expf(e[p] - mx) : 0.f;
            se += e[p];
        }
        float inv = 1.f / se;
        const __half* src = g_feats_h + (size_t)c * (HF * WF * DIM) + head * 32 + lane;
        #pragma unroll
        for (int p = 0; p < 16; p++) {
            if (!vis[p >> 2]) continue;
            int pp = p >> 2;
            float lx = __ldg(refcam + (((size_t)c * NQ + n) * PP + pp) * 2 + 0)
                     + g_soff[(size_t)n * 256 + head * 32 + p * 2 + 0];
            float ly = __ldg(refcam + (((size_t)c * NQ + n) * PP + pp) * 2 + 1)
                     + g_soff[(size_t)n * 256 + head * 32 + p * 2 + 1];
            acc += e[p] * inv * bilin_f16(src, HF, WF, lx, ly);
        }
    }
    g_sfused[(size_t)n * DIM + head * 32 + lane] = acc / (float)(cnt > 0 ? cnt : 1);
}

// ---------------- TF32 tensor-core GEMM -----------------------------------
// C[M,N] = act(A[M,K] @ B[K,N] + bias (+res)); act: 0=none,1=relu,2=tanh*scale
__device__ __forceinline__ unsigned f2tf(float x) {
    unsigned r;
    asm("cvt.rna.tf32.f32 %0, %1;" : "=r"(r) : "f"(x));
    return r;
}

template<int BM, int BN>
__global__ __launch_bounds__(256, 2)
void tgemm(const float* __restrict__ A, const float* __restrict__ B,
           const float* __restrict__ bias, const float* __restrict__ res,
           float* __restrict__ C, int M, int N, int K, int act, float scale) {
    constexpr int ASTR = 20;        // 16 + 4 pad
    constexpr int BSTR = BN + 4;
    constexpr int WM = (BM == 128) ? ((BN == 128) ? 4 : 8) : 4; // warps along M
    constexpr int WN = 8 / WM;                                   // warps along N
    constexpr int WCOLS = BN / WN;                               // cols per warp
    constexpr int MT = BM / (WM * 16);                           // m16 tiles per warp
    constexpr int NT = WCOLS / 8;                                // n8 tiles per warp
    constexpr int AF4 = BM / 64;                                 // float4/thread for A (BM*16/4/256)
    constexpr int BF4 = BN / 64;                                 // float4/thread for B (16*BN/4/256)

    __shared__ __align__(16) unsigned As[2][BM * ASTR];
    __shared__ __align__(16) unsigned Bs[2][16 * BSTR];

    int tid = threadIdx.x;
    int lane = tid & 31, wid = tid >> 5;
    int warp_m = wid % WM;
    int warp_n = wid / WM;
    int lr = lane >> 2;   // 0..7
    int lc = lane & 3;    // 0..3
    int bm = blockIdx.y * BM;
    int bn = blockIdx.x * BN;

    float4 pa[AF4], pb[BF4];

    float acc[MT][NT][4];
    #pragma unroll
    for (int mt = 0; mt < MT; mt++)
        #pragma unroll
        for (int nt = 0; nt < NT; nt++)
            #pragma unroll
            for (int r = 0; r < 4; r++) acc[mt][nt][r] = 0.f;

    // ---- prologue ----
    #pragma unroll
    for (int t = 0; t < AF4; t++) {
        int f = tid + t * 256;
        int row = f >> 2, c4 = f & 3;
        pa[t] = make_float4(0.f, 0.f, 0.f, 0.f);
        if (bm + row < M) pa[t] = *(const float4*)(A + (size_t)(bm + row) * K + c4 * 4);
    }
    #pragma unroll
    for (int t = 0; t < BF4; t++) {
        int f = tid + t * 256;
        int row = f / (BN / 4), c4 = f % (BN / 4);
        pb[t] = make_float4(0.f, 0.f, 0.f, 0.f);
        if (bn + c4 * 4 < N) pb[t] = *(const float4*)(B + (size_t)row * N + bn + c4 * 4);
    }
    #pragma unroll
    for (int t = 0; t < AF4; t++) {
        int f = tid + t * 256;
        int row = f >> 2, c4 = f & 3;
        unsigned* d = &As[0][row * ASTR + c4 * 4];
        d[0] = f2tf(pa[t].x); d[1] = f2tf(pa[t].y); d[2] = f2tf(pa[t].z); d[3] = f2tf(pa[t].w);
    }
    #pragma unroll
    for (int t = 0; t < BF4; t++) {
        int f = tid + t * 256;
        int row = f / (BN / 4), c4 = f % (BN / 4);
        unsigned* e = &Bs[0][row * BSTR + c4 * 4];
        e[0] = f2tf(pb[t].x); e[1] = f2tf(pb[t].y); e[2] = f2tf(pb[t].z); e[3] = f2tf(pb[t].w);
    }
    __syncthreads();

    int nk = K >> 4;
    for (int kt = 0; kt < nk; kt++) {
        int buf = kt & 1;
        if (kt + 1 < nk) {
            int k0 = (kt + 1) << 4;
            #pragma unroll
            for (int t = 0; t < AF4; t++) {
                int f = tid + t * 256;
                int row = f >> 2, c4 = f & 3;
                pa[t] = make_float4(0.f, 0.f, 0.f, 0.f);
                if (bm + row < M) pa[t] = *(const float4*)(A + (size_t)(bm + row) * K + k0 + c4 * 4);
            }
            #pragma unroll
            for (int t = 0; t < BF4; t++) {
                int f = tid + t * 256;
                int row = f / (BN / 4), c4 = f % (BN / 4);
                pb[t] = make_float4(0.f, 0.f, 0.f, 0.f);
                if (bn + c4 * 4 < N) pb[t] = *(const float4*)(B + (size_t)(k0 + row) * N + bn + c4 * 4);
            }
        }
        #pragma unroll
        for (int kk = 0; kk < 2; kk++) {
            unsigned afr[MT][4];
            #pragma unroll
            for (int mt = 0; mt < MT; mt++) {
                int r0 = (warp_m * (MT * 16) + mt * 16 + lr) * ASTR + kk * 8 + lc;
                afr[mt][0] = As[buf][r0];
                afr[mt][1] = As[buf][r0 + 8 * ASTR];
                afr[mt][2] = As[buf][r0 + 4];
                afr[mt][3] = As[buf][r0 + 8 * ASTR + 4];
            }
            #pragma unroll
            for (int nt = 0; nt < NT; nt++) {
                int cb = warp_n * WCOLS + nt * 8 + lr;
                unsigned b0 = Bs[buf][(kk * 8 + lc) * BSTR + cb];
                unsigned b1 = Bs[buf][(kk * 8 + 4 + lc) * BSTR + cb];
                #pragma unroll
                for (int mt = 0; mt < MT; mt++) {
                    asm volatile(
                        "mma.sync.aligned.m16n8k8.row.col.f32.tf32.tf32.f32 "
                        "{%0,%1,%2,%3}, {%4,%5,%6,%7}, {%8,%9}, {%0,%1,%2,%3};"
                        : "+f"(acc[mt][nt][0]), "+f"(acc[mt][nt][1]),
                          "+f"(acc[mt][nt][2]), "+f"(acc[mt][nt][3])
                        : "r"(afr[mt][0]), "r"(afr[mt][1]), "r"(afr[mt][2]), "r"(afr[mt][3]),
                          "r"(b0), "r"(b1));
                }
            }
        }
        if (kt + 1 < nk) {
            __syncthreads();
            int nb = buf ^ 1;
            #pragma unroll
            for (int t = 0; t < AF4; t++) {
                int f = tid + t * 256;
                int row = f >> 2, c4 = f & 3;
                unsigned* d = &As[nb][row * ASTR + c4 * 4];
                d[0] = f2tf(pa[t].x); d[1] = f2tf(pa[t].y); d[2] = f2tf(pa[t].z); d[3] = f2tf(pa[t].w);
            }
            #pragma unroll
            for (int t = 0; t < BF4; t++) {
                int f = tid + t * 256;
                int row = f / (BN / 4), c4 = f % (BN / 4);
                unsigned* e = &Bs[nb][row * BSTR + c4 * 4];
                e[0] = f2tf(pb[t].x); e[1] = f2tf(pb[t].y); e[2] = f2tf(pb[t].z); e[3] = f2tf(pb[t].w);
            }
            __syncthreads();
        }
    }

    // ---- epilogue ----
    #pragma unroll
    for (int mt = 0; mt < MT; mt++) {
        #pragma unroll
        for (int nt = 0; nt < NT; nt++) {
            int r0 = bm + warp_m * (MT * 16) + mt * 16 + lr;
            int c0 = bn + warp_n * WCOLS + nt * 8 + lc * 2;
            #pragma unroll
            for (int half = 0; half < 2; half++) {
                int row = r0 + half * 8;
                if (row >= M) continue;
                #pragma unroll
                for (int j = 0; j < 2; j++) {
                    int col = c0 + j;
                    if (col >= N) continue;
                    float v = acc[mt][nt][half * 2 + j] + __ldg(bias + col);
                    if (res) v += res[(size_t)row * N + col];
                    if (act == 1) v = fmaxf(v, 0.f);
                    else if (act == 2) v = tanhf(v) * scale;
                    C[(size_t)row * N + col] = v;
                }
            }
        }
    }
}

static inline void gemm128x128(const float* A, const float* B, const float* bias, const float* res,
                               float* C, int M, int N, int K, int act, float scale) {
    dim3 grid(N / 128, (M + 127) / 128);
    tgemm<128, 128><<<grid, 256>>>(A, B, bias, res, C, M, N, K, act, scale);
}
static inline void gemm128x64(const float* A, const float* B, const float* bias, const float* res,
                              float* C, int M, int N, int K, int act, float scale) {
    dim3 grid(N / 64, (M + 127) / 128);
    tgemm<128, 64><<<grid, 256>>>(A, B, bias, res, C, M, N, K, act, scale);
}
static inline void gemm64x64(const float* A, const float* B, const float* bias, const float* res,
                             float* C, int M, int N, int K, int act, float scale) {
    dim3 grid(N / 64, (M + 63) / 64);
    tgemm<64, 64><<<grid, 256>>>(A, B, bias, res, C, M, N, K, act, scale);
}

// ---------------- launch ----------------
extern "C" void kernel_launch(void* const* d_in, const int* in_sizes, int n_in,
                              void* d_out, int out_size) {
    const float* query   = (const float*)d_in[0];
    const float* prevbev = (const float*)d_in[1];
    const float* imfeats = (const float*)d_in[2];
    const float* ref2d   = (const float*)d_in[3];
    const float* refcam  = (const float*)d_in[4];
    const float* ego     = (const float*)d_in[5];
    const float* t_off_w = (const float*)d_in[6];
    const float* t_off_b = (const float*)d_in[7];
    const float* t_wt_w  = (const float*)d_in[8];
    const float* t_wt_b  = (const float*)d_in[9];
    const float* t_out_w = (const float*)d_in[10];
    const float* t_out_b = (const float*)d_in[11];
    const float* s_off_w = (const float*)d_in[12];
    const float* s_off_b = (const float*)d_in[13];
    const float* s_wt_w  = (const float*)d_in[14];
    const float* s_wt_b  = (const float*)d_in[15];
    const float* s_out_w = (const float*)d_in[16];
    const float* s_out_b = (const float*)d_in[17];
    const float* ffn_w1  = (const float*)d_in[18];
    const float* ffn_b1  = (const float*)d_in[19];
    const float* ffn_w2  = (const float*)d_in[20];
    const float* ffn_b2  = (const float*)d_in[21];
    const float* ln1_g   = (const float*)d_in[22];
    const float* ln1_b   = (const float*)d_in[23];
    const float* ln2_g   = (const float*)d_in[24];
    const float* ln2_b   = (const float*)d_in[25];
    const float* ln3_g   = (const float*)d_in[26];
    const float* ln3_b   = (const float*)d_in[27];
    const unsigned char* bev_mask = (const unsigned char*)d_in[28];

    float *ai, *toff, *twl, *tfused, *x, *q2, *soff, *swl, *sfused, *x2, *q3, *h;
    cudaGetSymbolAddress((void**)&ai, g_ai);
    cudaGetSymbolAddress((void**)&toff, g_toff);
    cudaGetSymbolAddress((void**)&twl, g_twl);
    cudaGetSymbolAddress((void**)&tfused, g_tfused);
    cudaGetSymbolAddress((void**)&x, g_x);
    cudaGetSymbolAddress((void**)&q2, g_q2);
    cudaGetSymbolAddress((void**)&soff, g_soff);
    cudaGetSymbolAddress((void**)&swl, g_swl);
    cudaGetSymbolAddress((void**)&sfused, g_sfused);
    cudaGetSymbolAddress((void**)&x2, g_x2);
    cudaGetSymbolAddress((void**)&q3, g_q3);
    cudaGetSymbolAddress((void**)&h, g_h);

    // 1) LN(query), LN(prev_bev) -> ai = [pb | q1]   (also the BEV maps, [H,W,C])
    ln1_kernel<<<NQ, 256>>>(query, prevbev, ln1_g, ln1_b);

    // prep: image feature transpose (fp16) + mask dtype detection (independent)
    transpose_feats<<<dim3(45, 8, NC), dim3(32, 8)>>>(imfeats);
    detect_mask<<<1, 256>>>(bev_mask, NC * NQ * PP);

    // 2) temporal offset / weight projections (tanh fused into epilogue)
    gemm128x64(ai, t_off_w, t_off_b, nullptr, toff, NQ, 128, 512, 2, T_RAD); // 158 blocks
    gemm64x64 (ai, t_wt_w,  t_wt_b,  nullptr, twl,  NQ, 64,  512, 0, 0.f);   // 157 blocks

    // 3) temporal deformable sampling
    temporal_kernel<<<NQ, 256>>>(ref2d, ego);

    // 4) x = query + tfused @ t_out_w + b
    gemm128x64(tfused, t_out_w, t_out_b, query, x, NQ, DIM, DIM, 0, 0.f);    // 316 blocks

    // 5) q2 = LN2(x)
    ln_kernel<<<NQ, 256>>>(x, ln2_g, ln2_b, q2);

    // 6) spatial offset / weight projections (tanh fused)
    gemm128x64(q2, s_off_w, s_off_b, nullptr, soff, NQ, 256, DIM, 2, S_RAD); // 316 blocks
    gemm64x64 (q2, s_wt_w,  s_wt_b,  nullptr, swl,  NQ, 128, DIM, 0, 0.f);   // 314 blocks

    // 7) spatial deformable cross-attention over 6 cameras (fp16 feats)
    spatial_kernel<<<NQ, 256>>>(refcam, bev_mask);

    // 8) x2 = x + sfused @ s_out_w + b
    gemm128x64(sfused, s_out_w, s_out_b, x, x2, NQ, DIM, DIM, 0, 0.f);       // 316 blocks

    // 9) q3 = LN3(x2); h = relu(q3 @ ffn_w1 + b1); out = x2 + h @ ffn_w2 + b2
    ln_kernel<<<NQ, 256>>>(x2, ln3_g, ln3_b, q3);
    gemm128x128(q3, ffn_w1, ffn_b1, nullptr, h, NQ, DFF, DIM, 1, 0.f);       // 632 blocks
    gemm128x64 (h, ffn_w2, ffn_b2, x2, (float*)d_out, NQ, DIM, DFF, 0, 0.f); // 316 blocks
}